// round 1
// baseline (speedup 1.0000x reference)
#include <cuda_runtime.h>

#define NN 2048
#define D  64

// Precomputed first-layer factors: A[i] = X[i] @ W1[0:64] + b1, B[j] = X[j] @ W1[64:128]
__device__ float g_A[NN * D];
__device__ float g_B[NN * D];

// ---------------------------------------------------------------------------
// Kernel 1: A/B precompute. One block per node row, 128 threads:
// threads 0..63 compute A columns, 64..127 compute B columns.
// ---------------------------------------------------------------------------
__global__ __launch_bounds__(128)
void k_pre(const float* __restrict__ X, const float* __restrict__ W1,
           const float* __restrict__ b1) {
    __shared__ float sx[D];
    const int i = blockIdx.x;
    const int t = threadIdx.x;
    if (t < D) sx[t] = X[i * D + t];
    __syncthreads();
    const int k = t & 63;
    const bool isA = t < 64;
    const float* w = W1 + (isA ? 0 : D * D) + k;   // W1 is [128][64] row-major
    float acc = isA ? b1[k] : 0.0f;
#pragma unroll
    for (int m = 0; m < D; m++) acc = fmaf(sx[m], w[m * D], acc);
    if (isA) g_A[i * D + k] = acc;
    else     g_B[i * D + k] = acc;
}

// ---------------------------------------------------------------------------
// Kernel 2: per-tile fused MLP.
//   Tile = BI x BJ = 8 i-rows x 16 j-cols = 128 pairs per CTA.
//   Phase 1: H1t[k][l] = relu(A[i_l][k] + B[j_l][k])        (b1 folded into A)
//   Phase 2: H2[l][c]  = relu(sum_k H1t[k][l] * W2[k][c] + b2[c])
//   Phase 3: out[p][o] = sum_c H2[l][c] * Wout[c][o] + bout[o]
// ---------------------------------------------------------------------------
#define BI 8
#define BJ 16

// smem layout (floats). uBuf is a union: H1t as [64][132] then H2 as [128][68].
#define SZ_UBUF   8704                      // max(64*132=8448, 128*68=8704)
#define OFF_W2    (SZ_UBUF)                 // 64*64 = 4096
#define OFF_A     (OFF_W2   + 4096)         // 8*65  = 520
#define OFF_B     (OFF_A    + 8*65)         // 16*65 = 1040
#define OFF_WOUT  (OFF_B    + 16*65)        // 64*9  = 576 (+16 pad for OOB-safe reads)
#define OFF_B2    (OFF_WOUT + 592)          // 64
#define OFF_BOUT  (OFF_B2   + 64)           // 9 (+pad)
#define SMEM_FLOATS (OFF_BOUT + 16)

__global__ __launch_bounds__(256, 3)
void k_edge(const float* __restrict__ W2, const float* __restrict__ b2,
            const float* __restrict__ We, const float* __restrict__ be,
            const float* __restrict__ Wt, const float* __restrict__ bt,
            float* __restrict__ out) {
    const int i0 = blockIdx.y * BI;
    const int j0 = blockIdx.x * BJ;
    if (j0 + BJ - 1 <= i0) return;   // whole tile below/on diagonal

    extern __shared__ float sm[];
    float* uBuf  = sm;
    float* sW2   = sm + OFF_W2;
    float* sA    = sm + OFF_A;
    float* sB    = sm + OFF_B;
    float* sWout = sm + OFF_WOUT;
    float* sb2   = sm + OFF_B2;
    float* sBout = sm + OFF_BOUT;

    const int tid = threadIdx.x;

    // ---- stage tile operands ----
    for (int idx = tid; idx < BI * D; idx += 256) {
        int li = idx >> 6, k = idx & 63;
        sA[li * 65 + k] = g_A[(i0 + li) * D + k];
    }
    for (int idx = tid; idx < BJ * D; idx += 256) {
        int lj = idx >> 6, k = idx & 63;
        sB[lj * 65 + k] = g_B[(j0 + lj) * D + k];
    }
    for (int idx = tid; idx < 4096; idx += 256) sW2[idx] = W2[idx];
    for (int idx = tid; idx < 576; idx += 256) {
        int k = idx / 9, o = idx - 9 * k;
        sWout[idx] = (o == 0) ? We[k] : Wt[k * 8 + (o - 1)];
    }
    if (tid < 64) sb2[tid] = b2[tid];
    if (tid < 9)  sBout[tid] = (tid == 0) ? be[0] : bt[tid - 1];
    __syncthreads();

    // ---- phase 1: H1t[k][l] = relu(A + B), K-major for the GEMM ----
    {
        const int l  = tid & 127;
        const int kg = (tid >> 7) * 32;
        const int li = l >> 4, lj = l & 15;
#pragma unroll
        for (int kk = 0; kk < 32; kk++) {
            int k = kg + kk;
            float h = sA[li * 65 + k] + sB[lj * 65 + k];
            uBuf[k * 132 + l] = fmaxf(h, 0.0f);
        }
    }
    __syncthreads();

    // ---- phase 2: register-tiled 128x64x64 GEMM ----
    const int tx = tid & 15;   // 4 output cols
    const int ty = tid >> 4;   // 8 output rows
    float acc[8][4];
#pragma unroll
    for (int rr = 0; rr < 8; rr++)
#pragma unroll
        for (int cc = 0; cc < 4; cc++) acc[rr][cc] = sb2[tx * 4 + cc];

    {
        const float* pH = uBuf + ty * 8;
        const float* pW = sW2  + tx * 4;
#pragma unroll 8
        for (int k = 0; k < 64; k++) {
            float4 a0 = *(const float4*)(pH + k * 132);
            float4 a1 = *(const float4*)(pH + k * 132 + 4);
            float4 w  = *(const float4*)(pW + k * 64);
            float av[8] = {a0.x, a0.y, a0.z, a0.w, a1.x, a1.y, a1.z, a1.w};
#pragma unroll
            for (int rr = 0; rr < 8; rr++) {
                acc[rr][0] = fmaf(av[rr], w.x, acc[rr][0]);
                acc[rr][1] = fmaf(av[rr], w.y, acc[rr][1]);
                acc[rr][2] = fmaf(av[rr], w.z, acc[rr][2]);
                acc[rr][3] = fmaf(av[rr], w.w, acc[rr][3]);
            }
        }
    }
    __syncthreads();   // everyone done reading H1t before overwriting uBuf

    // relu + stash H2 row-major [128][68]
#pragma unroll
    for (int rr = 0; rr < 8; rr++) {
        float4 v;
        v.x = fmaxf(acc[rr][0], 0.0f);
        v.y = fmaxf(acc[rr][1], 0.0f);
        v.z = fmaxf(acc[rr][2], 0.0f);
        v.w = fmaxf(acc[rr][3], 0.0f);
        *(float4*)(uBuf + (ty * 8 + rr) * 68 + tx * 4) = v;
    }
    __syncthreads();

    // ---- phase 3: 9-wide head + triu store ----
    {
        const int r     = tid >> 1;            // local pair 0..127
        const int half  = tid & 1;
        const int obase = half ? 5 : 0;
        const int no    = half ? 4 : 5;
        float a2[5];
#pragma unroll
        for (int q = 0; q < 5; q++) a2[q] = sBout[obase + q];
        const float* pH2 = uBuf + r * 68;
#pragma unroll
        for (int k4 = 0; k4 < 64; k4 += 4) {
            float4 v = *(const float4*)(pH2 + k4);
            float vv[4] = {v.x, v.y, v.z, v.w};
#pragma unroll
            for (int u = 0; u < 4; u++)
#pragma unroll
                for (int q = 0; q < 5; q++)
                    a2[q] = fmaf(vv[u], sWout[(k4 + u) * 9 + obase + q], a2[q]);
        }
        const int li = r >> 4, lj = r & 15;
        const int i = i0 + li, j = j0 + lj;
        if (j > i) {
            const int p = i * (2 * NN - i - 1) / 2 + (j - i - 1);
            float* po = out + p * 9 + obase;
#pragma unroll
            for (int q = 0; q < 5; q++)
                if (q < no) po[q] = a2[q];
        }
    }
}

// ---------------------------------------------------------------------------
extern "C" void kernel_launch(void* const* d_in, const int* in_sizes, int n_in,
                              void* d_out, int out_size) {
    const float* X  = (const float*)d_in[0];
    const float* W1 = (const float*)d_in[1];
    const float* b1 = (const float*)d_in[2];
    const float* W2 = (const float*)d_in[3];
    const float* b2 = (const float*)d_in[4];
    const float* We = (const float*)d_in[5];
    const float* be = (const float*)d_in[6];
    const float* Wt = (const float*)d_in[7];
    const float* bt = (const float*)d_in[8];
    float* out = (float*)d_out;

    cudaFuncSetAttribute(k_edge, cudaFuncAttributeMaxDynamicSharedMemorySize,
                         SMEM_FLOATS * (int)sizeof(float));

    k_pre<<<NN, 128>>>(X, W1, b1);

    dim3 grid(NN / BJ, NN / BI);   // (j-blocks, i-blocks)
    k_edge<<<grid, 256, SMEM_FLOATS * sizeof(float)>>>(W2, b2, We, be, Wt, bt, out);
}

// round 4
// speedup vs baseline: 1.0924x; 1.0924x over previous
#include <cuda_runtime.h>
#include <cuda_bf16.h>
#include <cstdint>

#define NN 2048
#define D  64
#define BI 8
#define BJ 16

__device__ __align__(256) float g_A[NN * D];
__device__ __align__(256) float g_B[NN * D];

// ---------------- smem layout (bytes) ----------------
// H1/H2 hi,lo: [128 rows][72 bf16] (144B stride, 16B aligned)
#define OFF_H1HI  0
#define OFF_H1LO  18432
#define OFF_W2HI  36864     // W2^T [64 rows=c][72 bf16]
#define OFF_W2LO  46080
#define OFF_WOHI  55296     // Wout^T [16 rows=o][72 bf16]
#define OFF_WOLO  57600
#define OFF_SA    59904     // [8][68] f32
#define OFF_SB    62080     // [16][68] f32
#define OFF_B2    66432     // 64 f32
#define OFF_BOUT  66688     // 16 f32
#define SMEM_BYTES 66752

__device__ __forceinline__ uint32_t smem_u32(const void* p) {
    uint32_t a;
    asm("{ .reg .u64 t; cvta.to.shared.u64 t, %1; cvt.u32.u64 %0, t; }" : "=r"(a) : "l"(p));
    return a;
}
__device__ __forceinline__ void ldsm_x4(uint32_t* r, uint32_t addr) {
    asm volatile("ldmatrix.sync.aligned.m8n8.x4.shared.b16 {%0,%1,%2,%3}, [%4];"
                 : "=r"(r[0]), "=r"(r[1]), "=r"(r[2]), "=r"(r[3]) : "r"(addr));
}
__device__ __forceinline__ void ldsm_x2(uint32_t* r, uint32_t addr) {
    asm volatile("ldmatrix.sync.aligned.m8n8.x2.shared.b16 {%0,%1}, [%2];"
                 : "=r"(r[0]), "=r"(r[1]) : "r"(addr));
}
__device__ __forceinline__ void mma_bf16(float* d, const uint32_t* a, const uint32_t* b) {
    asm volatile("mma.sync.aligned.m16n8k16.row.col.f32.bf16.bf16.f32 "
                 "{%0,%1,%2,%3}, {%4,%5,%6,%7}, {%8,%9}, {%0,%1,%2,%3};"
                 : "+f"(d[0]), "+f"(d[1]), "+f"(d[2]), "+f"(d[3])
                 : "r"(a[0]), "r"(a[1]), "r"(a[2]), "r"(a[3]), "r"(b[0]), "r"(b[1]));
}

union BU { __nv_bfloat162 b; uint32_t u; };
__device__ __forceinline__ uint32_t bsplit(float x, float y, uint32_t& lo) {
    BU h; h.b = __floats2bfloat162_rn(x, y);
    float rx = x - __bfloat162float(h.b.x);
    float ry = y - __bfloat162float(h.b.y);
    BU l; l.b = __floats2bfloat162_rn(rx, ry);
    lo = l.u;
    return h.u;
}

// ---------------------------------------------------------------------------
__global__ __launch_bounds__(128)
void k_pre(const float* __restrict__ X, const float* __restrict__ W1,
           const float* __restrict__ b1) {
    __shared__ float sx[D];
    const int i = blockIdx.x;
    const int t = threadIdx.x;
    if (t < D) sx[t] = X[i * D + t];
    __syncthreads();
    const int k = t & 63;
    const bool isA = t < 64;
    const float* w = W1 + (isA ? 0 : D * D) + k;
    float acc = isA ? b1[k] : 0.0f;
#pragma unroll
    for (int m = 0; m < D; m++) acc = fmaf(sx[m], w[m * D], acc);
    if (isA) g_A[i * D + k] = acc;
    else     g_B[i * D + k] = acc;
}

// ---------------------------------------------------------------------------
__global__ __launch_bounds__(128, 3)
void k_edge(const float* __restrict__ W2, const float* __restrict__ b2,
            const float* __restrict__ We, const float* __restrict__ be,
            const float* __restrict__ Wt, const float* __restrict__ bt,
            float* __restrict__ out) {
    const int i0 = blockIdx.y * BI;
    const int j0 = blockIdx.x * BJ;
    if (j0 + BJ - 1 <= i0) return;

    extern __shared__ char smc[];
    const uint32_t sb = smem_u32(smc);
    const int tid  = threadIdx.x;
    const int wid  = tid >> 5;
    const int lane = tid & 31;

    __nv_bfloat16* w2hi = (__nv_bfloat16*)(smc + OFF_W2HI);
    __nv_bfloat16* w2lo = (__nv_bfloat16*)(smc + OFF_W2LO);
    __nv_bfloat16* wohi = (__nv_bfloat16*)(smc + OFF_WOHI);
    __nv_bfloat16* wolo = (__nv_bfloat16*)(smc + OFF_WOLO);
    float* sA   = (float*)(smc + OFF_SA);
    float* sB   = (float*)(smc + OFF_SB);
    float* sb2f = (float*)(smc + OFF_B2);
    float* sbof = (float*)(smc + OFF_BOUT);

    // ---- stage weights (transposed, bf16 hi/lo) + biases + A/B rows ----
    for (int idx = tid; idx < 4096; idx += 128) {
        int c = idx >> 6, k = idx & 63;
        float v = W2[k * 64 + c];
        __nv_bfloat16 hi = __float2bfloat16_rn(v);
        w2hi[c * 72 + k] = hi;
        w2lo[c * 72 + k] = __float2bfloat16_rn(v - __bfloat162float(hi));
    }
    for (int idx = tid; idx < 1024; idx += 128) {
        int o = idx >> 6, k = idx & 63;
        float v = (o == 0) ? We[k] : (o <= 8 ? Wt[k * 8 + (o - 1)] : 0.0f);
        __nv_bfloat16 hi = __float2bfloat16_rn(v);
        wohi[o * 72 + k] = hi;
        wolo[o * 72 + k] = __float2bfloat16_rn(v - __bfloat162float(hi));
    }
    for (int idx = tid; idx < BI * D; idx += 128) {
        int li = idx >> 6, k = idx & 63;
        sA[li * 68 + k] = g_A[(i0 + li) * D + k];
    }
    for (int idx = tid; idx < BJ * D; idx += 128) {
        int lj = idx >> 6, k = idx & 63;
        sB[lj * 68 + k] = g_B[(j0 + lj) * D + k];
    }
    if (tid < 64) sb2f[tid] = b2[tid];
    if (tid < 16) sbof[tid] = (tid == 0) ? be[0] : (tid <= 8 ? bt[tid - 1] : 0.0f);
    __syncthreads();

    // ---- phase 1: H1 = relu(A+B) -> hi/lo bf16, row-major [row][72] ----
    {
        const int li = tid >> 4, lj = tid & 15;
        const float* pa = sA + li * 68;
        const float* pb = sB + lj * 68;
        const int rot = (tid >> 3) & 7;
#pragma unroll
        for (int k8i = 0; k8i < 8; k8i++) {
            int k8 = (k8i + rot) & 7;
            float4 a0 = *(const float4*)(pa + k8 * 8);
            float4 a1 = *(const float4*)(pa + k8 * 8 + 4);
            float4 b0 = *(const float4*)(pb + k8 * 8);
            float4 b1 = *(const float4*)(pb + k8 * 8 + 4);
            float h[8] = {fmaxf(a0.x + b0.x, 0.f), fmaxf(a0.y + b0.y, 0.f),
                          fmaxf(a0.z + b0.z, 0.f), fmaxf(a0.w + b0.w, 0.f),
                          fmaxf(a1.x + b1.x, 0.f), fmaxf(a1.y + b1.y, 0.f),
                          fmaxf(a1.z + b1.z, 0.f), fmaxf(a1.w + b1.w, 0.f)};
            uint32_t hi[4], lo[4];
#pragma unroll
            for (int v = 0; v < 4; v++) hi[v] = bsplit(h[2 * v], h[2 * v + 1], lo[v]);
            *(uint4*)(smc + OFF_H1HI + tid * 144 + k8 * 16) = make_uint4(hi[0], hi[1], hi[2], hi[3]);
            *(uint4*)(smc + OFF_H1LO + tid * 144 + k8 * 16) = make_uint4(lo[0], lo[1], lo[2], lo[3]);
        }
    }
    __syncthreads();

    // ---- main GEMM: warp = 64 rows x 32 cols ----
    const int mh = wid >> 1, nh = wid & 1;
    const int m0 = mh * 64, n0 = nh * 32;
    const int Lb = lane & 15;

    float b2c[4][2];
#pragma unroll
    for (int nb = 0; nb < 4; nb++) {
        b2c[nb][0] = sb2f[n0 + 8 * nb + 2 * (lane & 3)];
        b2c[nb][1] = sb2f[n0 + 8 * nb + 2 * (lane & 3) + 1];
    }

    float acc[4][4][4];
#pragma unroll
    for (int mb = 0; mb < 4; mb++)
#pragma unroll
        for (int nb = 0; nb < 4; nb++) {
            acc[mb][nb][0] = b2c[nb][0]; acc[mb][nb][1] = b2c[nb][1];
            acc[mb][nb][2] = b2c[nb][0]; acc[mb][nb][3] = b2c[nb][1];
        }

    {
        const uint32_t aBase = sb + (uint32_t)((m0 + (lane & 15)) * 144 + (lane >> 4) * 16);
        const uint32_t bBase = sb + (uint32_t)((n0 + (Lb & 7)) * 144 + (Lb >> 3) * 16);
#pragma unroll
        for (int kb = 0; kb < 4; kb++) {
            // B fragments for this k-chunk (hi/lo), 16 regs live
            uint32_t bh[4][2], bl[4][2];
#pragma unroll
            for (int nb = 0; nb < 4; nb++) {
                ldsm_x2(bh[nb], bBase + OFF_W2HI + nb * 8 * 144 + kb * 32);
                ldsm_x2(bl[nb], bBase + OFF_W2LO + nb * 8 * 144 + kb * 32);
            }
#pragma unroll
            for (int mb = 0; mb < 4; mb++) {
                uint32_t ahi[4], alo[4];
                uint32_t aa = aBase + mb * 16 * 144 + kb * 32;
                ldsm_x4(ahi, aa + OFF_H1HI);
                ldsm_x4(alo, aa + OFF_H1LO);
#pragma unroll
                for (int nb = 0; nb < 4; nb++) {
                    mma_bf16(acc[mb][nb], ahi, bh[nb]);
                    mma_bf16(acc[mb][nb], ahi, bl[nb]);
                    mma_bf16(acc[mb][nb], alo, bh[nb]);
                }
            }
        }
    }
    __syncthreads();   // all H1 reads done before overwrite with H2

    // ---- epilogue 1: relu + split -> H2 (reuse H1 buffers) ----
    {
        const int g = lane >> 2;
        const int cw = 2 * (lane & 3);
#pragma unroll
        for (int mb = 0; mb < 4; mb++) {
            int r0 = m0 + 16 * mb + g;
#pragma unroll
            for (int nb = 0; nb < 4; nb++) {
                int cb = (n0 + 8 * nb + cw) * 2;
                uint32_t l0, l1;
                uint32_t h0 = bsplit(fmaxf(acc[mb][nb][0], 0.f), fmaxf(acc[mb][nb][1], 0.f), l0);
                uint32_t h1 = bsplit(fmaxf(acc[mb][nb][2], 0.f), fmaxf(acc[mb][nb][3], 0.f), l1);
                *(uint32_t*)(smc + OFF_H1HI + r0 * 144 + cb)       = h0;
                *(uint32_t*)(smc + OFF_H1LO + r0 * 144 + cb)       = l0;
                *(uint32_t*)(smc + OFF_H1HI + (r0 + 8) * 144 + cb) = h1;
                *(uint32_t*)(smc + OFF_H1LO + (r0 + 8) * 144 + cb) = l1;
            }
        }
    }
    __syncthreads();

    // ---- head GEMM: warp = 32 rows x 16 cols ----
    {
        const int m0h = wid * 32;
        float hacc[2][2][4];
#pragma unroll
        for (int mb = 0; mb < 2; mb++)
#pragma unroll
            for (int nb = 0; nb < 2; nb++) {
                float v0 = sbof[8 * nb + 2 * (lane & 3)];
                float v1 = sbof[8 * nb + 2 * (lane & 3) + 1];
                hacc[mb][nb][0] = v0; hacc[mb][nb][1] = v1;
                hacc[mb][nb][2] = v0; hacc[mb][nb][3] = v1;
            }
        const uint32_t aBase = sb + (uint32_t)((m0h + (lane & 15)) * 144 + (lane >> 4) * 16);
        const uint32_t bBase = sb + (uint32_t)(((Lb & 7)) * 144 + (Lb >> 3) * 16);
#pragma unroll
        for (int kb = 0; kb < 4; kb++) {
            uint32_t bh2[2][2], bl2[2][2];
#pragma unroll
            for (int nb = 0; nb < 2; nb++) {
                ldsm_x2(bh2[nb], bBase + OFF_WOHI + nb * 8 * 144 + kb * 32);
                ldsm_x2(bl2[nb], bBase + OFF_WOLO + nb * 8 * 144 + kb * 32);
            }
#pragma unroll
            for (int mb = 0; mb < 2; mb++) {
                uint32_t ahi[4], alo[4];
                uint32_t aa = aBase + mb * 16 * 144 + kb * 32;
                ldsm_x4(ahi, aa + OFF_H1HI);
                ldsm_x4(alo, aa + OFF_H1LO);
#pragma unroll
                for (int nb = 0; nb < 2; nb++) {
                    mma_bf16(hacc[mb][nb], ahi, bh2[nb]);
                    mma_bf16(hacc[mb][nb], ahi, bl2[nb]);
                    mma_bf16(hacc[mb][nb], alo, bh2[nb]);
                }
            }
        }
        // ---- store: triu-packed, cols 0..8 ----
        const int g = lane >> 2;
        const int cw = 2 * (lane & 3);
#pragma unroll
        for (int mb = 0; mb < 2; mb++) {
#pragma unroll
            for (int half = 0; half < 2; half++) {
                int r = m0h + 16 * mb + g + 8 * half;
                int li = r >> 4, lj = r & 15;
                int i = i0 + li, j = j0 + lj;
                if (j > i) {
                    long p = (long)i * (2 * NN - i - 1) / 2 + (j - i - 1);
                    float* po = out + p * 9;
#pragma unroll
                    for (int nb = 0; nb < 2; nb++) {
                        int c0 = 8 * nb + cw;
                        if (c0 < 9)     po[c0]     = hacc[mb][nb][2 * half];
                        if (c0 + 1 < 9) po[c0 + 1] = hacc[mb][nb][2 * half + 1];
                    }
                }
            }
        }
    }
}

// ---------------------------------------------------------------------------
extern "C" void kernel_launch(void* const* d_in, const int* in_sizes, int n_in,
                              void* d_out, int out_size) {
    const float* X  = (const float*)d_in[0];
    const float* W1 = (const float*)d_in[1];
    const float* b1 = (const float*)d_in[2];
    const float* W2 = (const float*)d_in[3];
    const float* b2 = (const float*)d_in[4];
    const float* We = (const float*)d_in[5];
    const float* be = (const float*)d_in[6];
    const float* Wt = (const float*)d_in[7];
    const float* bt = (const float*)d_in[8];
    float* out = (float*)d_out;

    cudaFuncSetAttribute(k_edge, cudaFuncAttributeMaxDynamicSharedMemorySize, SMEM_BYTES);

    k_pre<<<NN, 128>>>(X, W1, b1);

    dim3 grid(NN / BJ, NN / BI);
    k_edge<<<grid, 128, SMEM_BYTES>>>(W2, b2, We, be, Wt, bt, out);
}

// round 5
// speedup vs baseline: 1.8031x; 1.6506x over previous
#include <cuda_runtime.h>
#include <cuda_bf16.h>
#include <cstdint>

#define NN 2048
#define D  64
#define BI 8
#define BJ 16
#define TILES_I 256
#define TILES_J 128
#define NTILES  (TILES_I * TILES_J)
#define GRID    592

__device__ __align__(256) float g_A[NN * D];
__device__ __align__(256) float g_B[NN * D];

// ---------------- smem layout (bytes) ----------------
#define OFF_H1HI  0
#define OFF_H1LO  18432
#define OFF_W2HI  36864     // W2^T [64 rows=c][72 bf16]
#define OFF_W2LO  46080
#define OFF_WOHI  55296     // Wout^T [16 rows=o][72 bf16]
#define OFF_WOLO  57600
#define OFF_SA    59904     // [8][68] f32
#define OFF_SB    62080     // [16][68] f32
#define OFF_B2    66432     // 64 f32
#define OFF_BOUT  66688     // 16 f32
#define SMEM_BYTES 66752

__device__ __forceinline__ uint32_t smem_u32(const void* p) {
    uint32_t a;
    asm("{ .reg .u64 t; cvta.to.shared.u64 t, %1; cvt.u32.u64 %0, t; }" : "=r"(a) : "l"(p));
    return a;
}
__device__ __forceinline__ void ldsm_x4(uint32_t* r, uint32_t addr) {
    asm volatile("ldmatrix.sync.aligned.m8n8.x4.shared.b16 {%0,%1,%2,%3}, [%4];"
                 : "=r"(r[0]), "=r"(r[1]), "=r"(r[2]), "=r"(r[3]) : "r"(addr));
}
__device__ __forceinline__ void ldsm_x2(uint32_t* r, uint32_t addr) {
    asm volatile("ldmatrix.sync.aligned.m8n8.x2.shared.b16 {%0,%1}, [%2];"
                 : "=r"(r[0]), "=r"(r[1]) : "r"(addr));
}
__device__ __forceinline__ void mma_bf16(float* d, const uint32_t* a, const uint32_t* b) {
    asm volatile("mma.sync.aligned.m16n8k16.row.col.f32.bf16.bf16.f32 "
                 "{%0,%1,%2,%3}, {%4,%5,%6,%7}, {%8,%9}, {%0,%1,%2,%3};"
                 : "+f"(d[0]), "+f"(d[1]), "+f"(d[2]), "+f"(d[3])
                 : "r"(a[0]), "r"(a[1]), "r"(a[2]), "r"(a[3]), "r"(b[0]), "r"(b[1]));
}

union BU { __nv_bfloat162 b; uint32_t u; };
__device__ __forceinline__ uint32_t bsplit(float x, float y, uint32_t& lo) {
    BU h; h.b = __floats2bfloat162_rn(x, y);
    float rx = x - __bfloat162float(h.b.x);
    float ry = y - __bfloat162float(h.b.y);
    BU l; l.b = __floats2bfloat162_rn(rx, ry);
    lo = l.u;
    return h.u;
}

// ---------------------------------------------------------------------------
__global__ __launch_bounds__(128)
void k_pre(const float* __restrict__ X, const float* __restrict__ W1,
           const float* __restrict__ b1) {
    __shared__ float sx[D];
    const int i = blockIdx.x;
    const int t = threadIdx.x;
    if (t < D) sx[t] = X[i * D + t];
    __syncthreads();
    const int k = t & 63;
    const bool isA = t < 64;
    const float* w = W1 + (isA ? 0 : D * D) + k;
    float acc = isA ? b1[k] : 0.0f;
#pragma unroll
    for (int m = 0; m < D; m++) acc = fmaf(sx[m], w[m * D], acc);
    if (isA) g_A[i * D + k] = acc;
    else     g_B[i * D + k] = acc;
}

// ---------------------------------------------------------------------------
__global__ __launch_bounds__(128, 3)
void k_edge(const float* __restrict__ W2, const float* __restrict__ b2,
            const float* __restrict__ We, const float* __restrict__ be,
            const float* __restrict__ Wt, const float* __restrict__ bt,
            float* __restrict__ out) {
    extern __shared__ char smc[];
    const uint32_t sb = smem_u32(smc);
    const int tid  = threadIdx.x;
    const int wid  = tid >> 5;
    const int lane = tid & 31;

    __nv_bfloat16* w2hi = (__nv_bfloat16*)(smc + OFF_W2HI);
    __nv_bfloat16* w2lo = (__nv_bfloat16*)(smc + OFF_W2LO);
    __nv_bfloat16* wohi = (__nv_bfloat16*)(smc + OFF_WOHI);
    __nv_bfloat16* wolo = (__nv_bfloat16*)(smc + OFF_WOLO);
    float* sA   = (float*)(smc + OFF_SA);
    float* sB   = (float*)(smc + OFF_SB);
    float* sb2f = (float*)(smc + OFF_B2);
    float* sbof = (float*)(smc + OFF_BOUT);

    // ---- ONE-TIME: stage weights (transposed, bf16 hi/lo) + biases ----
    for (int idx = tid; idx < 4096; idx += 128) {
        int c = idx >> 6, k = idx & 63;
        float v = W2[k * 64 + c];
        __nv_bfloat16 hi = __float2bfloat16_rn(v);
        w2hi[c * 72 + k] = hi;
        w2lo[c * 72 + k] = __float2bfloat16_rn(v - __bfloat162float(hi));
    }
    for (int idx = tid; idx < 1024; idx += 128) {
        int o = idx >> 6, k = idx & 63;
        float v = (o == 0) ? We[k] : (o <= 8 ? Wt[k * 8 + (o - 1)] : 0.0f);
        __nv_bfloat16 hi = __float2bfloat16_rn(v);
        wohi[o * 72 + k] = hi;
        wolo[o * 72 + k] = __float2bfloat16_rn(v - __bfloat162float(hi));
    }
    if (tid < 64) sb2f[tid] = b2[tid];
    if (tid < 16) sbof[tid] = (tid == 0) ? be[0] : (tid <= 8 ? bt[tid - 1] : 0.0f);
    __syncthreads();

    // per-warp constants
    const int mh = wid >> 1, nh = wid & 1;
    const int m0 = mh * 64, n0 = nh * 32;
    const int Lb = lane & 15;

    float b2c[4][2];
#pragma unroll
    for (int nb = 0; nb < 4; nb++) {
        b2c[nb][0] = sb2f[n0 + 8 * nb + 2 * (lane & 3)];
        b2c[nb][1] = sb2f[n0 + 8 * nb + 2 * (lane & 3) + 1];
    }
    float boc[2][2];
#pragma unroll
    for (int nb = 0; nb < 2; nb++) {
        boc[nb][0] = sbof[8 * nb + 2 * (lane & 3)];
        boc[nb][1] = sbof[8 * nb + 2 * (lane & 3) + 1];
    }

    const int p1li = tid >> 4, p1lj = tid & 15;
    const int rot = (tid >> 3) & 7;

    // ---- persistent tile loop ----
    for (int t = blockIdx.x; t < NTILES; t += GRID) {
        const int bi = t >> 7, bj = t & 127;
        const int i0 = bi * BI, j0 = bj * BJ;
        if (j0 + BJ - 1 <= i0) continue;

        // ---- stage A/B rows for this tile ----
        for (int idx = tid; idx < BI * D; idx += 128) {
            int li = idx >> 6, k = idx & 63;
            sA[li * 68 + k] = g_A[(i0 + li) * D + k];
        }
        for (int idx = tid; idx < BJ * D; idx += 128) {
            int lj = idx >> 6, k = idx & 63;
            sB[lj * 68 + k] = g_B[(j0 + lj) * D + k];
        }
        __syncthreads();   // staging visible; prev-iter head ldsm also done

        // ---- phase 1: H1 = relu(A+B) -> hi/lo bf16, [row][72] ----
        {
            const float* pa = sA + p1li * 68;
            const float* pb = sB + p1lj * 68;
#pragma unroll
            for (int k8i = 0; k8i < 8; k8i++) {
                int k8 = (k8i + rot) & 7;
                float4 a0 = *(const float4*)(pa + k8 * 8);
                float4 a1 = *(const float4*)(pa + k8 * 8 + 4);
                float4 b0 = *(const float4*)(pb + k8 * 8);
                float4 b1 = *(const float4*)(pb + k8 * 8 + 4);
                float h[8] = {fmaxf(a0.x + b0.x, 0.f), fmaxf(a0.y + b0.y, 0.f),
                              fmaxf(a0.z + b0.z, 0.f), fmaxf(a0.w + b0.w, 0.f),
                              fmaxf(a1.x + b1.x, 0.f), fmaxf(a1.y + b1.y, 0.f),
                              fmaxf(a1.z + b1.z, 0.f), fmaxf(a1.w + b1.w, 0.f)};
                uint32_t hi[4], lo[4];
#pragma unroll
                for (int v = 0; v < 4; v++) hi[v] = bsplit(h[2 * v], h[2 * v + 1], lo[v]);
                *(uint4*)(smc + OFF_H1HI + tid * 144 + k8 * 16) = make_uint4(hi[0], hi[1], hi[2], hi[3]);
                *(uint4*)(smc + OFF_H1LO + tid * 144 + k8 * 16) = make_uint4(lo[0], lo[1], lo[2], lo[3]);
            }
        }
        __syncthreads();

        // ---- main GEMM: warp = 64 rows x 32 cols ----
        float acc[4][4][4];
#pragma unroll
        for (int mb = 0; mb < 4; mb++)
#pragma unroll
            for (int nb = 0; nb < 4; nb++) {
                acc[mb][nb][0] = b2c[nb][0]; acc[mb][nb][1] = b2c[nb][1];
                acc[mb][nb][2] = b2c[nb][0]; acc[mb][nb][3] = b2c[nb][1];
            }
        {
            const uint32_t aBase = sb + (uint32_t)((m0 + (lane & 15)) * 144 + (lane >> 4) * 16);
            const uint32_t bBase = sb + (uint32_t)((n0 + (Lb & 7)) * 144 + (Lb >> 3) * 16);
#pragma unroll
            for (int kb = 0; kb < 4; kb++) {
                uint32_t bh[4][2], bl[4][2];
#pragma unroll
                for (int nb = 0; nb < 4; nb++) {
                    ldsm_x2(bh[nb], bBase + OFF_W2HI + nb * 8 * 144 + kb * 32);
                    ldsm_x2(bl[nb], bBase + OFF_W2LO + nb * 8 * 144 + kb * 32);
                }
#pragma unroll
                for (int mb = 0; mb < 4; mb++) {
                    uint32_t ahi[4], alo[4];
                    uint32_t aa = aBase + mb * 16 * 144 + kb * 32;
                    ldsm_x4(ahi, aa + OFF_H1HI);
                    ldsm_x4(alo, aa + OFF_H1LO);
#pragma unroll
                    for (int nb = 0; nb < 4; nb++) {
                        mma_bf16(acc[mb][nb], ahi, bh[nb]);
                        mma_bf16(acc[mb][nb], ahi, bl[nb]);
                        mma_bf16(acc[mb][nb], alo, bh[nb]);
                    }
                }
            }
        }
        __syncthreads();   // all H1 reads done before overwrite

        // ---- epilogue 1: relu + split -> H2 (reuse H1 buffers) ----
        {
            const int g = lane >> 2;
            const int cw = 2 * (lane & 3);
#pragma unroll
            for (int mb = 0; mb < 4; mb++) {
                int r0 = m0 + 16 * mb + g;
#pragma unroll
                for (int nb = 0; nb < 4; nb++) {
                    int cb = (n0 + 8 * nb + cw) * 2;
                    uint32_t l0, l1;
                    uint32_t h0 = bsplit(fmaxf(acc[mb][nb][0], 0.f), fmaxf(acc[mb][nb][1], 0.f), l0);
                    uint32_t h1 = bsplit(fmaxf(acc[mb][nb][2], 0.f), fmaxf(acc[mb][nb][3], 0.f), l1);
                    *(uint32_t*)(smc + OFF_H1HI + r0 * 144 + cb)       = h0;
                    *(uint32_t*)(smc + OFF_H1LO + r0 * 144 + cb)       = l0;
                    *(uint32_t*)(smc + OFF_H1HI + (r0 + 8) * 144 + cb) = h1;
                    *(uint32_t*)(smc + OFF_H1LO + (r0 + 8) * 144 + cb) = l1;
                }
            }
        }
        __syncthreads();

        // ---- head GEMM: warp = 32 rows x 16 cols, then triu store ----
        {
            const int m0h = wid * 32;
            float hacc[2][2][4];
#pragma unroll
            for (int mb = 0; mb < 2; mb++)
#pragma unroll
                for (int nb = 0; nb < 2; nb++) {
                    hacc[mb][nb][0] = boc[nb][0]; hacc[mb][nb][1] = boc[nb][1];
                    hacc[mb][nb][2] = boc[nb][0]; hacc[mb][nb][3] = boc[nb][1];
                }
            const uint32_t aBase = sb + (uint32_t)((m0h + (lane & 15)) * 144 + (lane >> 4) * 16);
            const uint32_t bBase = sb + (uint32_t)(((Lb & 7)) * 144 + (Lb >> 3) * 16);
#pragma unroll
            for (int kb = 0; kb < 4; kb++) {
                uint32_t bh2[2][2], bl2[2][2];
#pragma unroll
                for (int nb = 0; nb < 2; nb++) {
                    ldsm_x2(bh2[nb], bBase + OFF_WOHI + nb * 8 * 144 + kb * 32);
                    ldsm_x2(bl2[nb], bBase + OFF_WOLO + nb * 8 * 144 + kb * 32);
                }
#pragma unroll
                for (int mb = 0; mb < 2; mb++) {
                    uint32_t ahi[4], alo[4];
                    uint32_t aa = aBase + mb * 16 * 144 + kb * 32;
                    ldsm_x4(ahi, aa + OFF_H1HI);
                    ldsm_x4(alo, aa + OFF_H1LO);
#pragma unroll
                    for (int nb = 0; nb < 2; nb++) {
                        mma_bf16(hacc[mb][nb], ahi, bh2[nb]);
                        mma_bf16(hacc[mb][nb], ahi, bl2[nb]);
                        mma_bf16(hacc[mb][nb], alo, bh2[nb]);
                    }
                }
            }
            const int g = lane >> 2;
            const int cw = 2 * (lane & 3);
#pragma unroll
            for (int mb = 0; mb < 2; mb++) {
#pragma unroll
                for (int half = 0; half < 2; half++) {
                    int r = m0h + 16 * mb + g + 8 * half;
                    int li = r >> 4, lj = r & 15;
                    int i = i0 + li, j = j0 + lj;
                    if (j > i) {
                        long p = (long)i * (2 * NN - i - 1) / 2 + (j - i - 1);
                        float* po = out + p * 9;
#pragma unroll
                        for (int nb = 0; nb < 2; nb++) {
                            int c0 = 8 * nb + cw;
                            if (c0 < 9)     po[c0]     = hacc[mb][nb][2 * half];
                            if (c0 + 1 < 9) po[c0 + 1] = hacc[mb][nb][2 * half + 1];
                        }
                    }
                }
            }
        }
        __syncthreads();   // head reads done before next-iter phase1 overwrite
    }
}

// ---------------------------------------------------------------------------
extern "C" void kernel_launch(void* const* d_in, const int* in_sizes, int n_in,
                              void* d_out, int out_size) {
    const float* X  = (const float*)d_in[0];
    const float* W1 = (const float*)d_in[1];
    const float* b1 = (const float*)d_in[2];
    const float* W2 = (const float*)d_in[3];
    const float* b2 = (const float*)d_in[4];
    const float* We = (const float*)d_in[5];
    const float* be = (const float*)d_in[6];
    const float* Wt = (const float*)d_in[7];
    const float* bt = (const float*)d_in[8];
    float* out = (float*)d_out;

    cudaFuncSetAttribute(k_edge, cudaFuncAttributeMaxDynamicSharedMemorySize, SMEM_BYTES);

    k_pre<<<NN, 128>>>(X, W1, b1);
    k_edge<<<GRID, 128, SMEM_BYTES>>>(W2, b2, We, be, Wt, bt, out);
}

// round 6
// speedup vs baseline: 2.1588x; 1.1973x over previous
#include <cuda_runtime.h>
#include <cuda_bf16.h>
#include <cstdint>

#define NN 2048
#define D  64
#define BI 8
#define BJ 16
#define TILES_J 128
#define NTILES  (256 * 128)
#define GRID    296

__device__ __align__(256) float g_A[NN * D];
__device__ __align__(256) float g_B[NN * D];

// ---------------- smem layout (bytes) ----------------
#define OFF_H1HI  0          // [128 rows][144B]
#define OFF_H1LO  18432
#define OFF_W2HI  36864      // W2^T [64][72 bf16]
#define OFF_W2LO  46080
#define OFF_WOHI  55296      // Wout^T [16][72 bf16]
#define OFF_WOLO  57600
#define OFF_STG   59904      // 2 x (sA[8][68] + sB[16][68]) f32 = 2 x 6528
#define OFF_B2    72960      // 64 f32
#define OFF_BOUT  73216      // 16 f32
#define SMEM_BYTES 73280
#define STG_STRIDE 6528
#define STG_SB     2176      // sA part = 8*272

__device__ __forceinline__ uint32_t smem_u32(const void* p) {
    uint32_t a;
    asm("{ .reg .u64 t; cvta.to.shared.u64 t, %1; cvt.u32.u64 %0, t; }" : "=r"(a) : "l"(p));
    return a;
}
__device__ __forceinline__ void ldsm_x4(uint32_t* r, uint32_t addr) {
    asm volatile("ldmatrix.sync.aligned.m8n8.x4.shared.b16 {%0,%1,%2,%3}, [%4];"
                 : "=r"(r[0]), "=r"(r[1]), "=r"(r[2]), "=r"(r[3]) : "r"(addr));
}
__device__ __forceinline__ void ldsm_x2(uint32_t* r, uint32_t addr) {
    asm volatile("ldmatrix.sync.aligned.m8n8.x2.shared.b16 {%0,%1}, [%2];"
                 : "=r"(r[0]), "=r"(r[1]) : "r"(addr));
}
__device__ __forceinline__ void mma_bf16(float* d, const uint32_t* a, const uint32_t* b) {
    asm volatile("mma.sync.aligned.m16n8k16.row.col.f32.bf16.bf16.f32 "
                 "{%0,%1,%2,%3}, {%4,%5,%6,%7}, {%8,%9}, {%0,%1,%2,%3};"
                 : "+f"(d[0]), "+f"(d[1]), "+f"(d[2]), "+f"(d[3])
                 : "r"(a[0]), "r"(a[1]), "r"(a[2]), "r"(a[3]), "r"(b[0]), "r"(b[1]));
}
__device__ __forceinline__ void cp16(uint32_t dst, const void* src) {
    asm volatile("cp.async.ca.shared.global [%0], [%1], 16;" :: "r"(dst), "l"(src));
}
#define CP_COMMIT() asm volatile("cp.async.commit_group;" ::: "memory")
#define CP_WAIT0()  asm volatile("cp.async.wait_group 0;" ::: "memory")

union BU { __nv_bfloat162 b; uint32_t u; };
__device__ __forceinline__ uint32_t bsplit(float x, float y, uint32_t& lo) {
    BU h; h.b = __floats2bfloat162_rn(x, y);
    float rx = x - __bfloat162float(h.b.x);
    float ry = y - __bfloat162float(h.b.y);
    BU l; l.b = __floats2bfloat162_rn(rx, ry);
    lo = l.u;
    return h.u;
}
__device__ __forceinline__ bool tile_valid(int t) {
    int bi = t >> 7, bj = t & 127;
    return bj * BJ + BJ - 1 > bi * BI;
}

// ---------------------------------------------------------------------------
__global__ __launch_bounds__(128)
void k_pre(const float* __restrict__ X, const float* __restrict__ W1,
           const float* __restrict__ b1) {
    __shared__ float sx[D];
    const int i = blockIdx.x;
    const int t = threadIdx.x;
    if (t < D) sx[t] = X[i * D + t];
    __syncthreads();
    const int k = t & 63;
    const bool isA = t < 64;
    const float* w = W1 + (isA ? 0 : D * D) + k;
    float acc = isA ? b1[k] : 0.0f;
#pragma unroll
    for (int m = 0; m < D; m++) acc = fmaf(sx[m], w[m * D], acc);
    if (isA) g_A[i * D + k] = acc;
    else     g_B[i * D + k] = acc;
}

// ---------------------------------------------------------------------------
__global__ __launch_bounds__(256, 2)
void k_edge(const float* __restrict__ W2, const float* __restrict__ b2,
            const float* __restrict__ We, const float* __restrict__ be,
            const float* __restrict__ Wt, const float* __restrict__ bt,
            float* __restrict__ out) {
    extern __shared__ char smc[];
    const uint32_t sb = smem_u32(smc);
    const int tid  = threadIdx.x;
    const int wid  = tid >> 5;
    const int lane = tid & 31;

    __nv_bfloat16* w2hi = (__nv_bfloat16*)(smc + OFF_W2HI);
    __nv_bfloat16* w2lo = (__nv_bfloat16*)(smc + OFF_W2LO);
    __nv_bfloat16* wohi = (__nv_bfloat16*)(smc + OFF_WOHI);
    __nv_bfloat16* wolo = (__nv_bfloat16*)(smc + OFF_WOLO);
    float* sb2f = (float*)(smc + OFF_B2);
    float* sbof = (float*)(smc + OFF_BOUT);

    // ---- ONE-TIME: weights (transposed, bf16 hi/lo) + biases ----
    for (int idx = tid; idx < 4096; idx += 256) {
        int c = idx >> 6, k = idx & 63;
        float v = W2[k * 64 + c];
        __nv_bfloat16 hi = __float2bfloat16_rn(v);
        w2hi[c * 72 + k] = hi;
        w2lo[c * 72 + k] = __float2bfloat16_rn(v - __bfloat162float(hi));
    }
    for (int idx = tid; idx < 1024; idx += 256) {
        int o = idx >> 6, k = idx & 63;
        float v = (o == 0) ? We[k] : (o <= 8 ? Wt[k * 8 + (o - 1)] : 0.0f);
        __nv_bfloat16 hi = __float2bfloat16_rn(v);
        wohi[o * 72 + k] = hi;
        wolo[o * 72 + k] = __float2bfloat16_rn(v - __bfloat162float(hi));
    }
    if (tid < 64) sb2f[tid] = b2[tid];
    if (tid < 16) sbof[tid] = (tid == 0) ? be[0] : (tid <= 8 ? bt[tid - 1] : 0.0f);

    // ---- find first tile, issue its prefetch ----
    int t = blockIdx.x;
    while (t < NTILES && !tile_valid(t)) t += GRID;
    if (t < NTILES) {
        const int i0 = (t >> 7) * BI, j0 = (t & 127) * BJ;
        const uint32_t stg = sb + OFF_STG;
        for (int idx = tid; idx < 384; idx += 256) {
            if (idx < 128) {
                int li = idx >> 4, c = idx & 15;
                cp16(stg + li * 272 + c * 16, g_A + (i0 + li) * D + c * 4);
            } else {
                int q = idx - 128, lj = q >> 4, c = q & 15;
                cp16(stg + STG_SB + lj * 272 + c * 16, g_B + (j0 + lj) * D + c * 4);
            }
        }
    }
    CP_COMMIT();

    const int m0 = wid * 16;                    // warp's 16 rows
    const int Lb = lane & 15;
    const uint32_t aBase = sb + (uint32_t)((m0 + (lane & 15)) * 144 + (lane >> 4) * 16);
    const uint32_t bBase = sb + (uint32_t)((Lb & 7) * 144 + (Lb >> 3) * 16);
    const int g  = lane >> 2;
    const int cw = 2 * (lane & 3);

    // phase-1 mapping: 2 threads per row
    const int p1r  = tid >> 1;
    const int p1kh = tid & 1;
    const int p1li = p1r >> 4, p1lj = p1r & 15;

    int buf = 0;
    while (t < NTILES) {
        int nt = t + GRID;
        while (nt < NTILES && !tile_valid(nt)) nt += GRID;
        const int i0 = (t >> 7) * BI, j0 = (t & 127) * BJ;

        CP_WAIT0();
        __syncthreads();     // staged data ready; prev head reads of H1 done

        // ---- phase 1: H1 = relu(A+B) -> hi/lo bf16 ----
        {
            const float* sA = (const float*)(smc + OFF_STG + buf * STG_STRIDE);
            const float* sB = sA + (STG_SB / 4);
            const float* pa = sA + p1li * 68;
            const float* pb = sB + p1lj * 68;
#pragma unroll
            for (int k8i = 0; k8i < 4; k8i++) {
                int k8 = p1kh + 2 * k8i;
                float4 a0 = *(const float4*)(pa + k8 * 8);
                float4 a1 = *(const float4*)(pa + k8 * 8 + 4);
                float4 b0 = *(const float4*)(pb + k8 * 8);
                float4 b1 = *(const float4*)(pb + k8 * 8 + 4);
                float h[8] = {fmaxf(a0.x + b0.x, 0.f), fmaxf(a0.y + b0.y, 0.f),
                              fmaxf(a0.z + b0.z, 0.f), fmaxf(a0.w + b0.w, 0.f),
                              fmaxf(a1.x + b1.x, 0.f), fmaxf(a1.y + b1.y, 0.f),
                              fmaxf(a1.z + b1.z, 0.f), fmaxf(a1.w + b1.w, 0.f)};
                uint32_t hi[4], lo[4];
#pragma unroll
                for (int v = 0; v < 4; v++) hi[v] = bsplit(h[2 * v], h[2 * v + 1], lo[v]);
                *(uint4*)(smc + OFF_H1HI + p1r * 144 + k8 * 16) = make_uint4(hi[0], hi[1], hi[2], hi[3]);
                *(uint4*)(smc + OFF_H1LO + p1r * 144 + k8 * 16) = make_uint4(lo[0], lo[1], lo[2], lo[3]);
            }
        }
        __syncthreads();

        // ---- prefetch next tile into other buffer ----
        if (nt < NTILES) {
            const int ni0 = (nt >> 7) * BI, nj0 = (nt & 127) * BJ;
            const uint32_t stg = sb + OFF_STG + (buf ^ 1) * STG_STRIDE;
            for (int idx = tid; idx < 384; idx += 256) {
                if (idx < 128) {
                    int li = idx >> 4, c = idx & 15;
                    cp16(stg + li * 272 + c * 16, g_A + (ni0 + li) * D + c * 4);
                } else {
                    int q = idx - 128, lj = q >> 4, c = q & 15;
                    cp16(stg + STG_SB + lj * 272 + c * 16, g_B + (nj0 + lj) * D + c * 4);
                }
            }
        }
        CP_COMMIT();

        // ---- main GEMM: warp = 16 rows x 64 cols ----
        float acc[8][4];
#pragma unroll
        for (int nb = 0; nb < 8; nb++) {
            float v0 = sb2f[8 * nb + cw], v1 = sb2f[8 * nb + cw + 1];
            acc[nb][0] = v0; acc[nb][1] = v1; acc[nb][2] = v0; acc[nb][3] = v1;
        }
#pragma unroll
        for (int kb = 0; kb < 4; kb++) {
            uint32_t ahi[4], alo[4];
            ldsm_x4(ahi, aBase + OFF_H1HI + kb * 32);
            ldsm_x4(alo, aBase + OFF_H1LO + kb * 32);
#pragma unroll
            for (int nh = 0; nh < 2; nh++) {
                uint32_t bh[4][2], bl[4][2];
#pragma unroll
                for (int q = 0; q < 4; q++) {
                    int nb = nh * 4 + q;
                    ldsm_x2(bh[q], bBase + OFF_W2HI + nb * 8 * 144 + kb * 32);
                    ldsm_x2(bl[q], bBase + OFF_W2LO + nb * 8 * 144 + kb * 32);
                }
#pragma unroll
                for (int q = 0; q < 4; q++) {
                    mma_bf16(acc[nh * 4 + q], ahi, bh[q]);
                    mma_bf16(acc[nh * 4 + q], ahi, bl[q]);
                    mma_bf16(acc[nh * 4 + q], alo, bh[q]);
                }
            }
        }
        __syncthreads();   // all H1 reads done before overwrite

        // ---- epilogue: relu + split -> H2 (reuse H1 buffers) ----
        {
            int r0 = m0 + g;
#pragma unroll
            for (int nb = 0; nb < 8; nb++) {
                int cb = (8 * nb + cw) * 2;
                uint32_t l0, l1;
                uint32_t h0 = bsplit(fmaxf(acc[nb][0], 0.f), fmaxf(acc[nb][1], 0.f), l0);
                uint32_t h1 = bsplit(fmaxf(acc[nb][2], 0.f), fmaxf(acc[nb][3], 0.f), l1);
                *(uint32_t*)(smc + OFF_H1HI + r0 * 144 + cb)       = h0;
                *(uint32_t*)(smc + OFF_H1LO + r0 * 144 + cb)       = l0;
                *(uint32_t*)(smc + OFF_H1HI + (r0 + 8) * 144 + cb) = h1;
                *(uint32_t*)(smc + OFF_H1LO + (r0 + 8) * 144 + cb) = l1;
            }
        }
        __syncthreads();

        // ---- head GEMM: warp = 16 rows x 16 cols, then triu store ----
        {
            float hacc[2][4];
#pragma unroll
            for (int nb = 0; nb < 2; nb++) {
                float v0 = sbof[8 * nb + cw], v1 = sbof[8 * nb + cw + 1];
                hacc[nb][0] = v0; hacc[nb][1] = v1; hacc[nb][2] = v0; hacc[nb][3] = v1;
            }
#pragma unroll
            for (int kb = 0; kb < 4; kb++) {
                uint32_t bh2[2][2], bl2[2][2];
#pragma unroll
                for (int nb = 0; nb < 2; nb++) {
                    ldsm_x2(bh2[nb], bBase + OFF_WOHI + nb * 8 * 144 + kb * 32);
                    ldsm_x2(bl2[nb], bBase + OFF_WOLO + nb * 8 * 144 + kb * 32);
                }
                uint32_t ahi[4], alo[4];
                ldsm_x4(ahi, aBase + OFF_H1HI + kb * 32);
                ldsm_x4(alo, aBase + OFF_H1LO + kb * 32);
#pragma unroll
                for (int nb = 0; nb < 2; nb++) {
                    mma_bf16(hacc[nb], ahi, bh2[nb]);
                    mma_bf16(hacc[nb], ahi, bl2[nb]);
                    mma_bf16(hacc[nb], alo, bh2[nb]);
                }
            }
#pragma unroll
            for (int half = 0; half < 2; half++) {
                int r = m0 + g + 8 * half;
                int li = r >> 4, lj = r & 15;
                int i = i0 + li, j = j0 + lj;
                if (j > i) {
                    long p = (long)i * (2 * NN - i - 1) / 2 + (j - i - 1);
                    float* po = out + p * 9;
#pragma unroll
                    for (int nb = 0; nb < 2; nb++) {
                        int c0 = 8 * nb + cw;
                        if (c0 < 9)     po[c0]     = hacc[nb][2 * half];
                        if (c0 + 1 < 9) po[c0 + 1] = hacc[nb][2 * half + 1];
                    }
                }
            }
        }
        t = nt;
        buf ^= 1;
    }
}

// ---------------------------------------------------------------------------
extern "C" void kernel_launch(void* const* d_in, const int* in_sizes, int n_in,
                              void* d_out, int out_size) {
    const float* X  = (const float*)d_in[0];
    const float* W1 = (const float*)d_in[1];
    const float* b1 = (const float*)d_in[2];
    const float* W2 = (const float*)d_in[3];
    const float* b2 = (const float*)d_in[4];
    const float* We = (const float*)d_in[5];
    const float* be = (const float*)d_in[6];
    const float* Wt = (const float*)d_in[7];
    const float* bt = (const float*)d_in[8];
    float* out = (float*)d_out;

    cudaFuncSetAttribute(k_edge, cudaFuncAttributeMaxDynamicSharedMemorySize, SMEM_BYTES);

    k_pre<<<NN, 128>>>(X, W1, b1);
    k_edge<<<GRID, 256, SMEM_BYTES>>>(W2, b2, We, be, Wt, bt, out);
}

// round 7
// speedup vs baseline: 2.2346x; 1.0351x over previous
#include <cuda_runtime.h>
#include <cuda_bf16.h>
#include <cstdint>

#define NN 2048
#define D  64
#define BI 8
#define BJ 16
#define NTILES  (256 * 128)
#define GRID    444

__device__ __align__(256) float g_A[NN * D];
__device__ __align__(256) float g_B[NN * D];

// ---------------- smem layout (bytes) ----------------
#define OFF_H1HI  0          // [128 rows][144B]
#define OFF_H1LO  18432
#define OFF_W2HI  36864      // W2^T [64][72 bf16]
#define OFF_W2LO  46080
#define OFF_WOHI  55296      // Wout^T [16][72 bf16]
#define OFF_WOLO  57600
#define OFF_STG   59904      // 2 x (sA[8][68] + sB[16][68]) f32 = 2 x 6528
#define OFF_B2    72960      // 64 f32
#define OFF_BOUT  73216      // 16 f32
#define SMEM_BYTES 73280
#define STG_STRIDE 6528
#define STG_SB     2176      // sA part = 8*272

__device__ __forceinline__ uint32_t smem_u32(const void* p) {
    uint32_t a;
    asm("{ .reg .u64 t; cvta.to.shared.u64 t, %1; cvt.u32.u64 %0, t; }" : "=r"(a) : "l"(p));
    return a;
}
__device__ __forceinline__ void ldsm_x4(uint32_t* r, uint32_t addr) {
    asm volatile("ldmatrix.sync.aligned.m8n8.x4.shared.b16 {%0,%1,%2,%3}, [%4];"
                 : "=r"(r[0]), "=r"(r[1]), "=r"(r[2]), "=r"(r[3]) : "r"(addr));
}
__device__ __forceinline__ void ldsm_x2(uint32_t* r, uint32_t addr) {
    asm volatile("ldmatrix.sync.aligned.m8n8.x2.shared.b16 {%0,%1}, [%2];"
                 : "=r"(r[0]), "=r"(r[1]) : "r"(addr));
}
__device__ __forceinline__ void mma_bf16(float* d, const uint32_t* a, const uint32_t* b) {
    asm volatile("mma.sync.aligned.m16n8k16.row.col.f32.bf16.bf16.f32 "
                 "{%0,%1,%2,%3}, {%4,%5,%6,%7}, {%8,%9}, {%0,%1,%2,%3};"
                 : "+f"(d[0]), "+f"(d[1]), "+f"(d[2]), "+f"(d[3])
                 : "r"(a[0]), "r"(a[1]), "r"(a[2]), "r"(a[3]), "r"(b[0]), "r"(b[1]));
}
__device__ __forceinline__ void cp16(uint32_t dst, const void* src) {
    asm volatile("cp.async.ca.shared.global [%0], [%1], 16;" :: "r"(dst), "l"(src));
}
#define CP_COMMIT() asm volatile("cp.async.commit_group;" ::: "memory")
#define CP_WAIT0()  asm volatile("cp.async.wait_group 0;" ::: "memory")

union BU { __nv_bfloat162 b; uint32_t u; };
__device__ __forceinline__ uint32_t bsplit(float x, float y, uint32_t& lo) {
    BU h; h.b = __floats2bfloat162_rn(x, y);
    float rx = x - __bfloat162float(h.b.x);
    float ry = y - __bfloat162float(h.b.y);
    BU l; l.b = __floats2bfloat162_rn(rx, ry);
    lo = l.u;
    return h.u;
}
__device__ __forceinline__ bool tile_valid(int t) {
    int bi = t >> 7, bj = t & 127;
    return bj * BJ + BJ - 1 > bi * BI;
}

// ---------------------------------------------------------------------------
__global__ __launch_bounds__(128)
void k_pre(const float* __restrict__ X, const float* __restrict__ W1,
           const float* __restrict__ b1) {
    __shared__ float sx[D];
    const int i = blockIdx.x;
    const int t = threadIdx.x;
    if (t < D) sx[t] = X[i * D + t];
    __syncthreads();
    const int k = t & 63;
    const bool isA = t < 64;
    const float* w = W1 + (isA ? 0 : D * D) + k;
    float acc = isA ? b1[k] : 0.0f;
#pragma unroll
    for (int m = 0; m < D; m++) acc = fmaf(sx[m], w[m * D], acc);
    if (isA) g_A[i * D + k] = acc;
    else     g_B[i * D + k] = acc;
}

// ---------------------------------------------------------------------------
__global__ __launch_bounds__(256, 3)
void k_edge(const float* __restrict__ W2, const float* __restrict__ b2,
            const float* __restrict__ We, const float* __restrict__ be,
            const float* __restrict__ Wt, const float* __restrict__ bt,
            float* __restrict__ out) {
    extern __shared__ char smc[];
    const uint32_t sb = smem_u32(smc);
    const int tid  = threadIdx.x;
    const int wid  = tid >> 5;
    const int lane = tid & 31;

    __nv_bfloat16* w2hi = (__nv_bfloat16*)(smc + OFF_W2HI);
    __nv_bfloat16* w2lo = (__nv_bfloat16*)(smc + OFF_W2LO);
    __nv_bfloat16* wohi = (__nv_bfloat16*)(smc + OFF_WOHI);
    __nv_bfloat16* wolo = (__nv_bfloat16*)(smc + OFF_WOLO);
    float* sb2f = (float*)(smc + OFF_B2);
    float* sbof = (float*)(smc + OFF_BOUT);

    // ---- ONE-TIME: weights (transposed, bf16 hi/lo) + biases ----
    for (int idx = tid; idx < 4096; idx += 256) {
        int c = idx >> 6, k = idx & 63;
        float v = W2[k * 64 + c];
        __nv_bfloat16 hi = __float2bfloat16_rn(v);
        w2hi[c * 72 + k] = hi;
        w2lo[c * 72 + k] = __float2bfloat16_rn(v - __bfloat162float(hi));
    }
    for (int idx = tid; idx < 1024; idx += 256) {
        int o = idx >> 6, k = idx & 63;
        float v = (o == 0) ? We[k] : (o <= 8 ? Wt[k * 8 + (o - 1)] : 0.0f);
        __nv_bfloat16 hi = __float2bfloat16_rn(v);
        wohi[o * 72 + k] = hi;
        wolo[o * 72 + k] = __float2bfloat16_rn(v - __bfloat162float(hi));
    }
    if (tid < 64) sb2f[tid] = b2[tid];
    if (tid < 16) sbof[tid] = (tid == 0) ? be[0] : (tid <= 8 ? bt[tid - 1] : 0.0f);

    // ---- find first tile, issue its prefetch ----
    int t = blockIdx.x;
    while (t < NTILES && !tile_valid(t)) t += GRID;
    if (t < NTILES) {
        const int i0 = (t >> 7) * BI, j0 = (t & 127) * BJ;
        const uint32_t stg = sb + OFF_STG;
        for (int idx = tid; idx < 384; idx += 256) {
            if (idx < 128) {
                int li = idx >> 4, c = idx & 15;
                cp16(stg + li * 272 + c * 16, g_A + (i0 + li) * D + c * 4);
            } else {
                int q = idx - 128, lj = q >> 4, c = q & 15;
                cp16(stg + STG_SB + lj * 272 + c * 16, g_B + (j0 + lj) * D + c * 4);
            }
        }
    }
    CP_COMMIT();

    const int m0 = wid * 16;                    // warp's 16 rows
    const int Lb = lane & 15;
    const uint32_t aBase = sb + (uint32_t)((m0 + (lane & 15)) * 144 + (lane >> 4) * 16);
    const uint32_t bBase = sb + (uint32_t)((Lb & 7) * 144 + (Lb >> 3) * 16);
    const int g  = lane >> 2;
    const int cw = 2 * (lane & 3);

    // phase-1 mapping: 2 threads per row
    const int p1r  = tid >> 1;
    const int p1kh = tid & 1;
    const int p1li = p1r >> 4, p1lj = p1r & 15;

    int buf = 0;
    while (t < NTILES) {
        int nt = t + GRID;
        while (nt < NTILES && !tile_valid(nt)) nt += GRID;
        const int i0 = (t >> 7) * BI, j0 = (t & 127) * BJ;

        CP_WAIT0();
        __syncthreads();     // staged data ready; prev head reads of H1 done

        // ---- phase 1: H1 = relu(A+B) -> hi/lo bf16 ----
        {
            const float* sA = (const float*)(smc + OFF_STG + buf * STG_STRIDE);
            const float* sB = sA + (STG_SB / 4);
            const float* pa = sA + p1li * 68;
            const float* pb = sB + p1lj * 68;
#pragma unroll
            for (int k8i = 0; k8i < 4; k8i++) {
                int k8 = p1kh + 2 * k8i;
                float4 a0 = *(const float4*)(pa + k8 * 8);
                float4 a1 = *(const float4*)(pa + k8 * 8 + 4);
                float4 b0 = *(const float4*)(pb + k8 * 8);
                float4 b1 = *(const float4*)(pb + k8 * 8 + 4);
                float h[8] = {fmaxf(a0.x + b0.x, 0.f), fmaxf(a0.y + b0.y, 0.f),
                              fmaxf(a0.z + b0.z, 0.f), fmaxf(a0.w + b0.w, 0.f),
                              fmaxf(a1.x + b1.x, 0.f), fmaxf(a1.y + b1.y, 0.f),
                              fmaxf(a1.z + b1.z, 0.f), fmaxf(a1.w + b1.w, 0.f)};
                uint32_t hi[4], lo[4];
#pragma unroll
                for (int v = 0; v < 4; v++) hi[v] = bsplit(h[2 * v], h[2 * v + 1], lo[v]);
                *(uint4*)(smc + OFF_H1HI + p1r * 144 + k8 * 16) = make_uint4(hi[0], hi[1], hi[2], hi[3]);
                *(uint4*)(smc + OFF_H1LO + p1r * 144 + k8 * 16) = make_uint4(lo[0], lo[1], lo[2], lo[3]);
            }
        }
        __syncthreads();

        // ---- prefetch next tile into other buffer ----
        if (nt < NTILES) {
            const int ni0 = (nt >> 7) * BI, nj0 = (nt & 127) * BJ;
            const uint32_t stg = sb + OFF_STG + (buf ^ 1) * STG_STRIDE;
            for (int idx = tid; idx < 384; idx += 256) {
                if (idx < 128) {
                    int li = idx >> 4, c = idx & 15;
                    cp16(stg + li * 272 + c * 16, g_A + (ni0 + li) * D + c * 4);
                } else {
                    int q = idx - 128, lj = q >> 4, c = q & 15;
                    cp16(stg + STG_SB + lj * 272 + c * 16, g_B + (nj0 + lj) * D + c * 4);
                }
            }
        }
        CP_COMMIT();

        // ---- main GEMM: warp = 16 rows x 64 cols ----
        float acc[8][4];
#pragma unroll
        for (int nb = 0; nb < 8; nb++) {
            float v0 = sb2f[8 * nb + cw], v1 = sb2f[8 * nb + cw + 1];
            acc[nb][0] = v0; acc[nb][1] = v1; acc[nb][2] = v0; acc[nb][3] = v1;
        }
#pragma unroll
        for (int kb = 0; kb < 4; kb++) {
            uint32_t ahi[4], alo[4];
            ldsm_x4(ahi, aBase + OFF_H1HI + kb * 32);
            ldsm_x4(alo, aBase + OFF_H1LO + kb * 32);
#pragma unroll
            for (int nh = 0; nh < 2; nh++) {
                uint32_t bh[4][2], bl[4][2];
#pragma unroll
                for (int q = 0; q < 4; q++) {
                    int nb = nh * 4 + q;
                    ldsm_x2(bh[q], bBase + OFF_W2HI + nb * 8 * 144 + kb * 32);
                    ldsm_x2(bl[q], bBase + OFF_W2LO + nb * 8 * 144 + kb * 32);
                }
#pragma unroll
                for (int q = 0; q < 4; q++) {
                    mma_bf16(acc[nh * 4 + q], ahi, bh[q]);
                    mma_bf16(acc[nh * 4 + q], ahi, bl[q]);
                    mma_bf16(acc[nh * 4 + q], alo, bh[q]);
                }
            }
        }
        __syncthreads();   // all H1 reads done before overwrite

        // ---- epilogue: relu + split -> H2 (reuse H1 buffers) ----
        {
            int r0 = m0 + g;
#pragma unroll
            for (int nb = 0; nb < 8; nb++) {
                int cb = (8 * nb + cw) * 2;
                uint32_t l0, l1;
                uint32_t h0 = bsplit(fmaxf(acc[nb][0], 0.f), fmaxf(acc[nb][1], 0.f), l0);
                uint32_t h1 = bsplit(fmaxf(acc[nb][2], 0.f), fmaxf(acc[nb][3], 0.f), l1);
                *(uint32_t*)(smc + OFF_H1HI + r0 * 144 + cb)       = h0;
                *(uint32_t*)(smc + OFF_H1LO + r0 * 144 + cb)       = l0;
                *(uint32_t*)(smc + OFF_H1HI + (r0 + 8) * 144 + cb) = h1;
                *(uint32_t*)(smc + OFF_H1LO + (r0 + 8) * 144 + cb) = l1;
            }
        }
        __syncthreads();

        // ---- head GEMM: warp = 16 rows x 16 cols, then triu store ----
        {
            float hacc[2][4];
#pragma unroll
            for (int nb = 0; nb < 2; nb++) {
                float v0 = sbof[8 * nb + cw], v1 = sbof[8 * nb + cw + 1];
                hacc[nb][0] = v0; hacc[nb][1] = v1; hacc[nb][2] = v0; hacc[nb][3] = v1;
            }
#pragma unroll
            for (int kb = 0; kb < 4; kb++) {
                uint32_t bh2[2][2], bl2[2][2];
#pragma unroll
                for (int nb = 0; nb < 2; nb++) {
                    ldsm_x2(bh2[nb], bBase + OFF_WOHI + nb * 8 * 144 + kb * 32);
                    ldsm_x2(bl2[nb], bBase + OFF_WOLO + nb * 8 * 144 + kb * 32);
                }
                uint32_t ahi[4], alo[4];
                ldsm_x4(ahi, aBase + OFF_H1HI + kb * 32);
                ldsm_x4(alo, aBase + OFF_H1LO + kb * 32);
#pragma unroll
                for (int nb = 0; nb < 2; nb++) {
                    mma_bf16(hacc[nb], ahi, bh2[nb]);
                    mma_bf16(hacc[nb], ahi, bl2[nb]);
                    mma_bf16(hacc[nb], alo, bh2[nb]);
                }
            }
#pragma unroll
            for (int half = 0; half < 2; half++) {
                int r = m0 + g + 8 * half;
                int li = r >> 4, lj = r & 15;
                int i = i0 + li, j = j0 + lj;
                if (j > i) {
                    long p = (long)i * (2 * NN - i - 1) / 2 + (j - i - 1);
                    float* po = out + p * 9;
#pragma unroll
                    for (int nb = 0; nb < 2; nb++) {
                        int c0 = 8 * nb + cw;
                        if (c0 < 9)     po[c0]     = hacc[nb][2 * half];
                        if (c0 + 1 < 9) po[c0 + 1] = hacc[nb][2 * half + 1];
                    }
                }
            }
        }
        t = nt;
        buf ^= 1;
    }
}

// ---------------------------------------------------------------------------
extern "C" void kernel_launch(void* const* d_in, const int* in_sizes, int n_in,
                              void* d_out, int out_size) {
    const float* X  = (const float*)d_in[0];
    const float* W1 = (const float*)d_in[1];
    const float* b1 = (const float*)d_in[2];
    const float* W2 = (const float*)d_in[3];
    const float* b2 = (const float*)d_in[4];
    const float* We = (const float*)d_in[5];
    const float* be = (const float*)d_in[6];
    const float* Wt = (const float*)d_in[7];
    const float* bt = (const float*)d_in[8];
    float* out = (float*)d_out;

    cudaFuncSetAttribute(k_edge, cudaFuncAttributeMaxDynamicSharedMemorySize, SMEM_BYTES);

    k_pre<<<NN, 128>>>(X, W1, b1);
    k_edge<<<GRID, 256, SMEM_BYTES>>>(W2, b2, We, be, Wt, bt, out);
}

// round 8
// speedup vs baseline: 2.5939x; 1.1608x over previous
#include <cuda_runtime.h>
#include <cuda_bf16.h>
#include <cstdint>

#define NN 2048
#define D  64
#define BI 16
#define BJ 16
#define NTILES  (128 * 128)
#define GRID    296

__device__ __align__(256) float g_A[NN * D];
__device__ __align__(256) float g_B[NN * D];

// ---------------- smem layout (bytes) ----------------
#define OFF_H1HI  0           // [256 rows][144B]
#define OFF_H1LO  36864
#define OFF_W2HI  73728       // W2^T [64][72 bf16]
#define OFF_W2LO  82944
#define OFF_WOHI  92160       // Wout^T [16][72 bf16]
#define OFF_WOLO  94464
#define OFF_STG   96768       // 2 x (sA[16][68] + sB[16][68]) f32 = 2 x 8704
#define OFF_B2    114176      // 64 f32
#define OFF_BOUT  114432      // 16 f32
#define SMEM_BYTES 114496
#define STG_STRIDE 8704
#define STG_SB     4352       // sA part = 16*272

__device__ __forceinline__ uint32_t smem_u32(const void* p) {
    uint32_t a;
    asm("{ .reg .u64 t; cvta.to.shared.u64 t, %1; cvt.u32.u64 %0, t; }" : "=r"(a) : "l"(p));
    return a;
}
__device__ __forceinline__ void ldsm_x4(uint32_t* r, uint32_t addr) {
    asm volatile("ldmatrix.sync.aligned.m8n8.x4.shared.b16 {%0,%1,%2,%3}, [%4];"
                 : "=r"(r[0]), "=r"(r[1]), "=r"(r[2]), "=r"(r[3]) : "r"(addr));
}
__device__ __forceinline__ void ldsm_x2(uint32_t* r, uint32_t addr) {
    asm volatile("ldmatrix.sync.aligned.m8n8.x2.shared.b16 {%0,%1}, [%2];"
                 : "=r"(r[0]), "=r"(r[1]) : "r"(addr));
}
__device__ __forceinline__ void mma_bf16(float* d, const uint32_t* a, const uint32_t* b) {
    asm volatile("mma.sync.aligned.m16n8k16.row.col.f32.bf16.bf16.f32 "
                 "{%0,%1,%2,%3}, {%4,%5,%6,%7}, {%8,%9}, {%0,%1,%2,%3};"
                 : "+f"(d[0]), "+f"(d[1]), "+f"(d[2]), "+f"(d[3])
                 : "r"(a[0]), "r"(a[1]), "r"(a[2]), "r"(a[3]), "r"(b[0]), "r"(b[1]));
}
__device__ __forceinline__ void cp16(uint32_t dst, const void* src) {
    asm volatile("cp.async.ca.shared.global [%0], [%1], 16;" :: "r"(dst), "l"(src));
}
#define CP_COMMIT() asm volatile("cp.async.commit_group;" ::: "memory")
#define CP_WAIT0()  asm volatile("cp.async.wait_group 0;" ::: "memory")

union BU { __nv_bfloat162 b; uint32_t u; };
__device__ __forceinline__ uint32_t bsplit(float x, float y, uint32_t& lo) {
    BU h; h.b = __floats2bfloat162_rn(x, y);
    float rx = x - __bfloat162float(h.b.x);
    float ry = y - __bfloat162float(h.b.y);
    BU l; l.b = __floats2bfloat162_rn(rx, ry);
    lo = l.u;
    return h.u;
}
__device__ __forceinline__ bool tile_valid(int t) {
    return (t & 127) >= (t >> 7);      // bj >= bi
}

// ---------------------------------------------------------------------------
__global__ __launch_bounds__(128)
void k_pre(const float* __restrict__ X, const float* __restrict__ W1,
           const float* __restrict__ b1) {
    __shared__ float sx[D];
    const int i = blockIdx.x;
    const int t = threadIdx.x;
    if (t < D) sx[t] = X[i * D + t];
    __syncthreads();
    const int k = t & 63;
    const bool isA = t < 64;
    const float* w = W1 + (isA ? 0 : D * D) + k;
    float acc = isA ? b1[k] : 0.0f;
#pragma unroll
    for (int m = 0; m < D; m++) acc = fmaf(sx[m], w[m * D], acc);
    if (isA) g_A[i * D + k] = acc;
    else     g_B[i * D + k] = acc;
}

// ---------------------------------------------------------------------------
__global__ __launch_bounds__(256, 2)
void k_edge(const float* __restrict__ W2, const float* __restrict__ b2,
            const float* __restrict__ We, const float* __restrict__ be,
            const float* __restrict__ Wt, const float* __restrict__ bt,
            float* __restrict__ out) {
    extern __shared__ char smc[];
    const uint32_t sb = smem_u32(smc);
    const int tid  = threadIdx.x;
    const int wid  = tid >> 5;
    const int lane = tid & 31;

    __nv_bfloat16* w2hi = (__nv_bfloat16*)(smc + OFF_W2HI);
    __nv_bfloat16* w2lo = (__nv_bfloat16*)(smc + OFF_W2LO);
    __nv_bfloat16* wohi = (__nv_bfloat16*)(smc + OFF_WOHI);
    __nv_bfloat16* wolo = (__nv_bfloat16*)(smc + OFF_WOLO);
    float* sb2f = (float*)(smc + OFF_B2);
    float* sbof = (float*)(smc + OFF_BOUT);

    // ---- ONE-TIME: weights (transposed, bf16 hi/lo) + biases ----
    for (int idx = tid; idx < 4096; idx += 256) {
        int c = idx >> 6, k = idx & 63;
        float v = W2[k * 64 + c];
        __nv_bfloat16 hi = __float2bfloat16_rn(v);
        w2hi[c * 72 + k] = hi;
        w2lo[c * 72 + k] = __float2bfloat16_rn(v - __bfloat162float(hi));
    }
    for (int idx = tid; idx < 1024; idx += 256) {
        int o = idx >> 6, k = idx & 63;
        float v = (o == 0) ? We[k] : (o <= 8 ? Wt[k * 8 + (o - 1)] : 0.0f);
        __nv_bfloat16 hi = __float2bfloat16_rn(v);
        wohi[o * 72 + k] = hi;
        wolo[o * 72 + k] = __float2bfloat16_rn(v - __bfloat162float(hi));
    }
    if (tid < 64) sb2f[tid] = b2[tid];
    if (tid < 16) sbof[tid] = (tid == 0) ? be[0] : (tid <= 8 ? bt[tid - 1] : 0.0f);

    // ---- find first tile, issue its prefetch ----
    int t = blockIdx.x;
    while (t < NTILES && !tile_valid(t)) t += GRID;
    if (t < NTILES) {
        const int i0 = (t >> 7) * BI, j0 = (t & 127) * BJ;
        const uint32_t stg = sb + OFF_STG;
        for (int idx = tid; idx < 512; idx += 256) {
            if (idx < 256) {
                int li = idx >> 4, c = idx & 15;
                cp16(stg + li * 272 + c * 16, g_A + (i0 + li) * D + c * 4);
            } else {
                int q = idx - 256, lj = q >> 4, c = q & 15;
                cp16(stg + STG_SB + lj * 272 + c * 16, g_B + (j0 + lj) * D + c * 4);
            }
        }
    }
    CP_COMMIT();

    const int m0 = wid * 32;                    // warp's 32 rows
    const int Lb = lane & 15;
    const uint32_t aBase = sb + (uint32_t)((m0 + (lane & 15)) * 144 + (lane >> 4) * 16);
    const uint32_t bBase = sb + (uint32_t)((Lb & 7) * 144 + (Lb >> 3) * 16);
    const int g  = lane >> 2;
    const int cw = 2 * (lane & 3);

    // phase-1 mapping: 1 thread per row (256 rows)
    const int p1li = tid >> 4, p1lj = tid & 15;
    const int rot  = (tid >> 3) & 7;

    int buf = 0;
    while (t < NTILES) {
        int nt = t + GRID;
        while (nt < NTILES && !tile_valid(nt)) nt += GRID;
        const int i0 = (t >> 7) * BI, j0 = (t & 127) * BJ;

        CP_WAIT0();
        __syncthreads();     // staged data ready; prev head reads of H1 done

        // ---- phase 1: H1 = relu(A+B) -> hi/lo bf16, row = tid ----
        {
            const float* sA = (const float*)(smc + OFF_STG + buf * STG_STRIDE);
            const float* sB = sA + (STG_SB / 4);
            const float* pa = sA + p1li * 68;
            const float* pb = sB + p1lj * 68;
#pragma unroll
            for (int k8i = 0; k8i < 8; k8i++) {
                int k8 = (k8i + rot) & 7;
                float4 a0 = *(const float4*)(pa + k8 * 8);
                float4 a1 = *(const float4*)(pa + k8 * 8 + 4);
                float4 b0 = *(const float4*)(pb + k8 * 8);
                float4 b1 = *(const float4*)(pb + k8 * 8 + 4);
                float h[8] = {fmaxf(a0.x + b0.x, 0.f), fmaxf(a0.y + b0.y, 0.f),
                              fmaxf(a0.z + b0.z, 0.f), fmaxf(a0.w + b0.w, 0.f),
                              fmaxf(a1.x + b1.x, 0.f), fmaxf(a1.y + b1.y, 0.f),
                              fmaxf(a1.z + b1.z, 0.f), fmaxf(a1.w + b1.w, 0.f)};
                uint32_t hi[4], lo[4];
#pragma unroll
                for (int v = 0; v < 4; v++) hi[v] = bsplit(h[2 * v], h[2 * v + 1], lo[v]);
                *(uint4*)(smc + OFF_H1HI + tid * 144 + k8 * 16) = make_uint4(hi[0], hi[1], hi[2], hi[3]);
                *(uint4*)(smc + OFF_H1LO + tid * 144 + k8 * 16) = make_uint4(lo[0], lo[1], lo[2], lo[3]);
            }
        }
        __syncthreads();

        // ---- prefetch next tile into other buffer ----
        if (nt < NTILES) {
            const int ni0 = (nt >> 7) * BI, nj0 = (nt & 127) * BJ;
            const uint32_t stg = sb + OFF_STG + (buf ^ 1) * STG_STRIDE;
            for (int idx = tid; idx < 512; idx += 256) {
                if (idx < 256) {
                    int li = idx >> 4, c = idx & 15;
                    cp16(stg + li * 272 + c * 16, g_A + (ni0 + li) * D + c * 4);
                } else {
                    int q = idx - 256, lj = q >> 4, c = q & 15;
                    cp16(stg + STG_SB + lj * 272 + c * 16, g_B + (nj0 + lj) * D + c * 4);
                }
            }
        }
        CP_COMMIT();

        // ---- main GEMM: warp = 32 rows x 64 cols ----
        float acc[2][8][4];
#pragma unroll
        for (int mb = 0; mb < 2; mb++)
#pragma unroll
            for (int nb = 0; nb < 8; nb++) {
                float v0 = sb2f[8 * nb + cw], v1 = sb2f[8 * nb + cw + 1];
                acc[mb][nb][0] = v0; acc[mb][nb][1] = v1;
                acc[mb][nb][2] = v0; acc[mb][nb][3] = v1;
            }
#pragma unroll
        for (int kb = 0; kb < 4; kb++) {
            uint32_t ahi[2][4], alo[2][4];
#pragma unroll
            for (int mb = 0; mb < 2; mb++) {
                uint32_t aa = aBase + mb * 16 * 144 + kb * 32;
                ldsm_x4(ahi[mb], aa + OFF_H1HI);
                ldsm_x4(alo[mb], aa + OFF_H1LO);
            }
#pragma unroll
            for (int nh = 0; nh < 2; nh++) {
                uint32_t bh[4][2], bl[4][2];
#pragma unroll
                for (int q = 0; q < 4; q++) {
                    int nb = nh * 4 + q;
                    ldsm_x2(bh[q], bBase + OFF_W2HI + nb * 8 * 144 + kb * 32);
                    ldsm_x2(bl[q], bBase + OFF_W2LO + nb * 8 * 144 + kb * 32);
                }
#pragma unroll
                for (int mb = 0; mb < 2; mb++)
#pragma unroll
                    for (int q = 0; q < 4; q++) {
                        mma_bf16(acc[mb][nh * 4 + q], ahi[mb], bh[q]);
                        mma_bf16(acc[mb][nh * 4 + q], ahi[mb], bl[q]);
                        mma_bf16(acc[mb][nh * 4 + q], alo[mb], bh[q]);
                    }
            }
        }
        __syncthreads();   // all H1 reads done before overwrite

        // ---- epilogue: relu + split -> H2 (reuse H1 buffers) ----
        {
#pragma unroll
            for (int mb = 0; mb < 2; mb++) {
                int r0 = m0 + 16 * mb + g;
#pragma unroll
                for (int nb = 0; nb < 8; nb++) {
                    int cb = (8 * nb + cw) * 2;
                    uint32_t l0, l1;
                    uint32_t h0 = bsplit(fmaxf(acc[mb][nb][0], 0.f), fmaxf(acc[mb][nb][1], 0.f), l0);
                    uint32_t h1 = bsplit(fmaxf(acc[mb][nb][2], 0.f), fmaxf(acc[mb][nb][3], 0.f), l1);
                    *(uint32_t*)(smc + OFF_H1HI + r0 * 144 + cb)       = h0;
                    *(uint32_t*)(smc + OFF_H1LO + r0 * 144 + cb)       = l0;
                    *(uint32_t*)(smc + OFF_H1HI + (r0 + 8) * 144 + cb) = h1;
                    *(uint32_t*)(smc + OFF_H1LO + (r0 + 8) * 144 + cb) = l1;
                }
            }
        }
        __syncthreads();

        // ---- head GEMM: warp = 32 rows x 16 cols, then triu store ----
        {
            float hacc[2][2][4];
#pragma unroll
            for (int mb = 0; mb < 2; mb++)
#pragma unroll
                for (int nb = 0; nb < 2; nb++) {
                    float v0 = sbof[8 * nb + cw], v1 = sbof[8 * nb + cw + 1];
                    hacc[mb][nb][0] = v0; hacc[mb][nb][1] = v1;
                    hacc[mb][nb][2] = v0; hacc[mb][nb][3] = v1;
                }
#pragma unroll
            for (int kb = 0; kb < 4; kb++) {
                uint32_t bh2[2][2], bl2[2][2];
#pragma unroll
                for (int nb = 0; nb < 2; nb++) {
                    ldsm_x2(bh2[nb], bBase + OFF_WOHI + nb * 8 * 144 + kb * 32);
                    ldsm_x2(bl2[nb], bBase + OFF_WOLO + nb * 8 * 144 + kb * 32);
                }
#pragma unroll
                for (int mb = 0; mb < 2; mb++) {
                    uint32_t ahi[4], alo[4];
                    uint32_t aa = aBase + mb * 16 * 144 + kb * 32;
                    ldsm_x4(ahi, aa + OFF_H1HI);
                    ldsm_x4(alo, aa + OFF_H1LO);
#pragma unroll
                    for (int nb = 0; nb < 2; nb++) {
                        mma_bf16(hacc[mb][nb], ahi, bh2[nb]);
                        mma_bf16(hacc[mb][nb], ahi, bl2[nb]);
                        mma_bf16(hacc[mb][nb], alo, bh2[nb]);
                    }
                }
            }
#pragma unroll
            for (int mb = 0; mb < 2; mb++)
#pragma unroll
                for (int half = 0; half < 2; half++) {
                    int r = m0 + 16 * mb + g + 8 * half;
                    int li = r >> 4, lj = r & 15;
                    int i = i0 + li, j = j0 + lj;
                    if (j > i) {
                        long p = (long)i * (2 * NN - i - 1) / 2 + (j - i - 1);
                        float* po = out + p * 9;
#pragma unroll
                        for (int nb = 0; nb < 2; nb++) {
                            int c0 = 8 * nb + cw;
                            if (c0 < 9)     po[c0]     = hacc[mb][nb][2 * half];
                            if (c0 + 1 < 9) po[c0 + 1] = hacc[mb][nb][2 * half + 1];
                        }
                    }
                }
        }
        t = nt;
        buf ^= 1;
    }
}

// ---------------------------------------------------------------------------
extern "C" void kernel_launch(void* const* d_in, const int* in_sizes, int n_in,
                              void* d_out, int out_size) {
    const float* X  = (const float*)d_in[0];
    const float* W1 = (const float*)d_in[1];
    const float* b1 = (const float*)d_in[2];
    const float* W2 = (const float*)d_in[3];
    const float* b2 = (const float*)d_in[4];
    const float* We = (const float*)d_in[5];
    const float* be = (const float*)d_in[6];
    const float* Wt = (const float*)d_in[7];
    const float* bt = (const float*)d_in[8];
    float* out = (float*)d_out;

    cudaFuncSetAttribute(k_edge, cudaFuncAttributeMaxDynamicSharedMemorySize, SMEM_BYTES);

    k_pre<<<NN, 128>>>(X, W1, b1);
    k_edge<<<GRID, 256, SMEM_BYTES>>>(W2, b2, We, be, Wt, bt, out);
}